// round 1
// baseline (speedup 1.0000x reference)
#include <cuda_runtime.h>

#define N_NODES 10000
#define N_EDGES 640000
#define D 128

// ---------------- scratch (device globals; no allocation allowed) ----------
__device__ float g_agg[N_NODES * D];
__device__ float g_h1[N_NODES * D];
__device__ float g_h2[N_NODES * D];
__device__ float g_p[N_NODES * 4];
__device__ float g_invdeg[N_NODES];
__device__ int g_deg[N_NODES];
__device__ int g_rowoff[N_NODES];
__device__ int g_cursor[N_NODES];
__device__ int g_csr[N_EDGES];

// ---------------- CSR build ------------------------------------------------
__global__ void k_zero_deg() {
    int i = blockIdx.x * blockDim.x + threadIdx.x;
    if (i < N_NODES) g_deg[i] = 0;
}

__global__ void k_count(const int* __restrict__ dst) {
    int e = blockIdx.x * blockDim.x + threadIdx.x;
    if (e < N_EDGES) atomicAdd(&g_deg[dst[e]], 1);
}

// one block, 1024 threads, chunk=10 -> covers 10240 >= 10000
__global__ void k_scan() {
    __shared__ int ssum[1024];
    int t = threadIdx.x;
    int base = t * 10;
    int s = 0;
#pragma unroll
    for (int i = 0; i < 10; i++) {
        int idx = base + i;
        if (idx < N_NODES) s += g_deg[idx];
    }
    ssum[t] = s;
    __syncthreads();
    for (int off = 1; off < 1024; off <<= 1) {
        int v = (t >= off) ? ssum[t - off] : 0;
        __syncthreads();
        ssum[t] += v;
        __syncthreads();
    }
    int run = (t > 0) ? ssum[t - 1] : 0;
#pragma unroll
    for (int i = 0; i < 10; i++) {
        int idx = base + i;
        if (idx < N_NODES) {
            g_rowoff[idx] = run;
            g_cursor[idx] = run;
            int d = g_deg[idx];
            g_invdeg[idx] = 1.0f / (float)(d < 1 ? 1 : d);
            run += d;
        }
    }
}

__global__ void k_fill(const int* __restrict__ src, const int* __restrict__ dst) {
    int e = blockIdx.x * blockDim.x + threadIdx.x;
    if (e < N_EDGES) {
        int p = atomicAdd(&g_cursor[dst[e]], 1);
        g_csr[p] = src[e];
    }
}

// ---------------- pull-based mean aggregation ------------------------------
// one warp per node; lane l owns feature chunk [4l, 4l+4)
__global__ void k_agg(const float* __restrict__ feat) {
    int gid = blockIdx.x * blockDim.x + threadIdx.x;
    int n = gid >> 5;
    int lane = gid & 31;
    if (n >= N_NODES) return;
    int beg = g_rowoff[n];
    int d = g_deg[n];
    float ax = 0.f, ay = 0.f, az = 0.f, aw = 0.f;
    for (int base = 0; base < d; base += 32) {
        int my = -1;
        if (base + lane < d) my = g_csr[beg + base + lane];
        int cnt = min(32, d - base);
        int j = 0;
        for (; j + 4 <= cnt; j += 4) {
            int s0 = __shfl_sync(0xffffffffu, my, j);
            int s1 = __shfl_sync(0xffffffffu, my, j + 1);
            int s2 = __shfl_sync(0xffffffffu, my, j + 2);
            int s3 = __shfl_sync(0xffffffffu, my, j + 3);
            float4 v0 = *(const float4*)(feat + (size_t)s0 * D + lane * 4);
            float4 v1 = *(const float4*)(feat + (size_t)s1 * D + lane * 4);
            float4 v2 = *(const float4*)(feat + (size_t)s2 * D + lane * 4);
            float4 v3 = *(const float4*)(feat + (size_t)s3 * D + lane * 4);
            ax += v0.x + v1.x + v2.x + v3.x;
            ay += v0.y + v1.y + v2.y + v3.y;
            az += v0.z + v1.z + v2.z + v3.z;
            aw += v0.w + v1.w + v2.w + v3.w;
        }
        for (; j < cnt; j++) {
            int s0 = __shfl_sync(0xffffffffu, my, j);
            float4 v0 = *(const float4*)(feat + (size_t)s0 * D + lane * 4);
            ax += v0.x; ay += v0.y; az += v0.z; aw += v0.w;
        }
    }
    float inv = g_invdeg[n];
    float4 r;
    r.x = ax * inv; r.y = ay * inv; r.z = az * inv; r.w = aw * inv;
    *(float4*)(g_agg + (size_t)n * D + lane * 4) = r;
}

// ---------------- fused SAGE layer: out = act(in@Ws + agg@Wn + b) ----------
// 148 blocks x 544 threads; 68 nodes/block; thread computes 4 nodes x 4 cols.
// smem: Ws[128x128], Wn[128x128], A^T[128][68], B^T[128][68]  (~200 KB)
#define LAYER_THREADS 544
#define TILE_N 68
#define SA_STRIDE 68

__global__ void __launch_bounds__(LAYER_THREADS, 1)
k_layer(const float* __restrict__ in, const float* __restrict__ agg,
        const float* __restrict__ Wself, const float* __restrict__ Wneigh,
        const float* __restrict__ bias, float* __restrict__ out, int relu) {
    extern __shared__ float smf[];
    float* sWs = smf;                       // D*D
    float* sWn = sWs + D * D;               // D*D
    float* sA = sWn + D * D;                // D*SA_STRIDE  (A^T: [k][n])
    float* sB = sA + D * SA_STRIDE;         // D*SA_STRIDE

    int tid = threadIdx.x;
    int nb = blockIdx.x * TILE_N;

    // load weights (row-major [k][c]) as float4
    for (int i = tid; i < D * D / 4; i += LAYER_THREADS) {
        ((float4*)sWs)[i] = ((const float4*)Wself)[i];
        ((float4*)sWn)[i] = ((const float4*)Wneigh)[i];
    }
    // load node rows transposed into sA/sB
    for (int idx = tid; idx < TILE_N * 32; idx += LAYER_THREADS) {
        int n = idx >> 5;
        int kq = idx & 31;
        int gn = nb + n;
        float4 va = make_float4(0.f, 0.f, 0.f, 0.f);
        float4 vb = va;
        if (gn < N_NODES) {
            va = *(const float4*)(in + (size_t)gn * D + kq * 4);
            vb = *(const float4*)(agg + (size_t)gn * D + kq * 4);
        }
        sA[(kq * 4 + 0) * SA_STRIDE + n] = va.x;
        sA[(kq * 4 + 1) * SA_STRIDE + n] = va.y;
        sA[(kq * 4 + 2) * SA_STRIDE + n] = va.z;
        sA[(kq * 4 + 3) * SA_STRIDE + n] = va.w;
        sB[(kq * 4 + 0) * SA_STRIDE + n] = vb.x;
        sB[(kq * 4 + 1) * SA_STRIDE + n] = vb.y;
        sB[(kq * 4 + 2) * SA_STRIDE + n] = vb.z;
        sB[(kq * 4 + 3) * SA_STRIDE + n] = vb.w;
    }
    __syncthreads();

    int tx = tid & 31;     // col group: cols 4*tx..4*tx+3
    int ty = tid >> 5;     // node group: nodes 4*ty..4*ty+3 (ty in 0..16)

    float acc[4][4];
#pragma unroll
    for (int i = 0; i < 4; i++)
#pragma unroll
        for (int j = 0; j < 4; j++) acc[i][j] = 0.f;

#pragma unroll 4
    for (int k = 0; k < D; k++) {
        float4 a4 = *(const float4*)(sA + k * SA_STRIDE + 4 * ty);
        float4 b4 = *(const float4*)(sB + k * SA_STRIDE + 4 * ty);
        float4 w4 = *(const float4*)(sWs + k * D + 4 * tx);
        float4 n4 = *(const float4*)(sWn + k * D + 4 * tx);
        float av[4] = {a4.x, a4.y, a4.z, a4.w};
        float bv[4] = {b4.x, b4.y, b4.z, b4.w};
        float wv[4] = {w4.x, w4.y, w4.z, w4.w};
        float nv[4] = {n4.x, n4.y, n4.z, n4.w};
#pragma unroll
        for (int i = 0; i < 4; i++)
#pragma unroll
            for (int j = 0; j < 4; j++)
                acc[i][j] += av[i] * wv[j] + bv[i] * nv[j];
    }

    float4 bq = *(const float4*)(bias + 4 * tx);
    float bb[4] = {bq.x, bq.y, bq.z, bq.w};
#pragma unroll
    for (int i = 0; i < 4; i++) {
        int gn = nb + 4 * ty + i;
        if (gn < N_NODES) {
            float4 o;
            o.x = acc[i][0] + bb[0];
            o.y = acc[i][1] + bb[1];
            o.z = acc[i][2] + bb[2];
            o.w = acc[i][3] + bb[3];
            if (relu) {
                o.x = fmaxf(o.x, 0.f); o.y = fmaxf(o.y, 0.f);
                o.z = fmaxf(o.z, 0.f); o.w = fmaxf(o.w, 0.f);
            }
            *(float4*)(out + (size_t)gn * D + 4 * tx) = o;
        }
    }
}

// ---------------- per-node predictor projections: p = h2 @ [Wtop | Wbot] ---
// one warp per node; 4 dot products of length 128 via warp reduction
__global__ void k_pred(const float* __restrict__ h2, const float* __restrict__ Wp) {
    int gid = blockIdx.x * blockDim.x + threadIdx.x;
    int n = gid >> 5;
    int lane = gid & 31;
    if (n >= N_NODES) return;
    float4 h = *(const float4*)(h2 + (size_t)n * D + lane * 4);
    const float4* W4 = (const float4*)Wp;       // Wp is [256][2] row-major
    float4 wa = W4[2 * lane];                   // rows 4l, 4l+1
    float4 wb = W4[2 * lane + 1];               // rows 4l+2, 4l+3
    float4 wc = W4[64 + 2 * lane];              // rows 128+4l, 128+4l+1
    float4 wd = W4[64 + 2 * lane + 1];
    float p0 = h.x * wa.x + h.y * wa.z + h.z * wb.x + h.w * wb.z;
    float p1 = h.x * wa.y + h.y * wa.w + h.z * wb.y + h.w * wb.w;
    float p2 = h.x * wc.x + h.y * wc.z + h.z * wd.x + h.w * wd.z;
    float p3 = h.x * wc.y + h.y * wc.w + h.z * wd.y + h.w * wd.w;
#pragma unroll
    for (int off = 16; off > 0; off >>= 1) {
        p0 += __shfl_down_sync(0xffffffffu, p0, off);
        p1 += __shfl_down_sync(0xffffffffu, p1, off);
        p2 += __shfl_down_sync(0xffffffffu, p2, off);
        p3 += __shfl_down_sync(0xffffffffu, p3, off);
    }
    if (lane == 0) {
        float4 r = make_float4(p0, p1, p2, p3);
        *(float4*)(g_p + (size_t)n * 4) = r;
    }
}

// ---------------- edge scores: out[e] = p[src].xy + p[dst].zw + b ----------
__global__ void k_edge(const int* __restrict__ src, const int* __restrict__ dst,
                       const float* __restrict__ bpred, float* __restrict__ out) {
    int e = blockIdx.x * blockDim.x + threadIdx.x;
    if (e >= N_EDGES) return;
    float b0 = __ldg(bpred);
    float b1 = __ldg(bpred + 1);
    float4 ps = *(const float4*)(g_p + (size_t)src[e] * 4);
    float4 pd = *(const float4*)(g_p + (size_t)dst[e] * 4);
    float2 o;
    o.x = ps.x + pd.z + b0;
    o.y = ps.y + pd.w + b1;
    *(float2*)(out + (size_t)e * 2) = o;
}

// ---------------- launcher -------------------------------------------------
extern "C" void kernel_launch(void* const* d_in, const int* in_sizes, int n_in,
                              void* d_out, int out_size) {
    const float* x = (const float*)d_in[0];
    const int* src = (const int*)d_in[1];
    const int* dst = (const int*)d_in[2];
    const float* Wself1 = (const float*)d_in[3];
    const float* Wneigh1 = (const float*)d_in[4];
    const float* b1 = (const float*)d_in[5];
    const float* Wself2 = (const float*)d_in[6];
    const float* Wneigh2 = (const float*)d_in[7];
    const float* b2 = (const float*)d_in[8];
    const float* Wpred = (const float*)d_in[9];
    const float* bpred = (const float*)d_in[10];
    float* out = (float*)d_out;

    size_t smem_bytes = (size_t)(2 * D * D + 2 * D * SA_STRIDE) * sizeof(float);
    cudaFuncSetAttribute(k_layer, cudaFuncAttributeMaxDynamicSharedMemorySize,
                         (int)smem_bytes);

    float *p_agg, *p_h1, *p_h2;
    cudaGetSymbolAddress((void**)&p_agg, g_agg);
    cudaGetSymbolAddress((void**)&p_h1, g_h1);
    cudaGetSymbolAddress((void**)&p_h2, g_h2);

    const int TPB = 256;
    // CSR build (reused by both layers)
    k_zero_deg<<<(N_NODES + TPB - 1) / TPB, TPB>>>();
    k_count<<<(N_EDGES + TPB - 1) / TPB, TPB>>>(dst);
    k_scan<<<1, 1024>>>();
    k_fill<<<(N_EDGES + TPB - 1) / TPB, TPB>>>(src, dst);

    int agg_blocks = (N_NODES * 32 + TPB - 1) / TPB;   // warp per node
    // layer 1
    k_agg<<<agg_blocks, TPB>>>(x);
    k_layer<<<148, LAYER_THREADS, smem_bytes>>>(x, p_agg, Wself1, Wneigh1, b1,
                                                p_h1, 1);
    // layer 2
    k_agg<<<agg_blocks, TPB>>>(p_h1);
    k_layer<<<148, LAYER_THREADS, smem_bytes>>>(p_h1, p_agg, Wself2, Wneigh2, b2,
                                                p_h2, 0);
    // edge predictor (factored through per-node projections)
    k_pred<<<agg_blocks, TPB>>>(p_h2, Wpred);
    k_edge<<<(N_EDGES + TPB - 1) / TPB, TPB>>>(src, dst, bpred, out);
}

// round 2
// speedup vs baseline: 1.2225x; 1.2225x over previous
#include <cuda_runtime.h>

#define N_NODES 10000
#define N_EDGES 640000
#define D 128
#define CAP 160   // padded CSR bucket capacity (mean deg 64, sigma 8)

// ---------------- scratch (device globals; no allocation allowed) ----------
__device__ float g_agg[N_NODES * D];
__device__ float g_h1[N_NODES * D];
__device__ float g_h2[N_NODES * D];
__device__ float2 g_ps[N_NODES];
__device__ float2 g_pd[N_NODES];
__device__ int g_cnt[N_NODES];
__device__ int g_csr[N_NODES * CAP];

// ---------------- padded CSR fill: 4 edges per thread ----------------------
__global__ void k_fill(const int* __restrict__ src, const int* __restrict__ dst) {
    int t = blockIdx.x * blockDim.x + threadIdx.x;
    if (t * 4 >= N_EDGES) return;
    int4 s = ((const int4*)src)[t];
    int4 d = ((const int4*)dst)[t];
    int p0 = atomicAdd(&g_cnt[d.x], 1);
    int p1 = atomicAdd(&g_cnt[d.y], 1);
    int p2 = atomicAdd(&g_cnt[d.z], 1);
    int p3 = atomicAdd(&g_cnt[d.w], 1);
    if (p0 < CAP) g_csr[d.x * CAP + p0] = s.x;
    if (p1 < CAP) g_csr[d.y * CAP + p1] = s.y;
    if (p2 < CAP) g_csr[d.z * CAP + p2] = s.z;
    if (p3 < CAP) g_csr[d.w * CAP + p3] = s.w;
}

// ---------------- pull-based mean aggregation ------------------------------
// one warp per node; lane l owns feature chunk [4l, 4l+4)
__global__ void k_agg(const float* __restrict__ feat) {
    int gid = blockIdx.x * blockDim.x + threadIdx.x;
    int n = gid >> 5;
    int lane = gid & 31;
    if (n >= N_NODES) return;
    int beg = n * CAP;
    int d = g_cnt[n];
    float ax = 0.f, ay = 0.f, az = 0.f, aw = 0.f;
    for (int base = 0; base < d; base += 32) {
        int my = -1;
        if (base + lane < d) my = g_csr[beg + base + lane];
        int cnt = min(32, d - base);
        int j = 0;
        for (; j + 4 <= cnt; j += 4) {
            int s0 = __shfl_sync(0xffffffffu, my, j);
            int s1 = __shfl_sync(0xffffffffu, my, j + 1);
            int s2 = __shfl_sync(0xffffffffu, my, j + 2);
            int s3 = __shfl_sync(0xffffffffu, my, j + 3);
            float4 v0 = *(const float4*)(feat + (size_t)s0 * D + lane * 4);
            float4 v1 = *(const float4*)(feat + (size_t)s1 * D + lane * 4);
            float4 v2 = *(const float4*)(feat + (size_t)s2 * D + lane * 4);
            float4 v3 = *(const float4*)(feat + (size_t)s3 * D + lane * 4);
            ax += v0.x + v1.x + v2.x + v3.x;
            ay += v0.y + v1.y + v2.y + v3.y;
            az += v0.z + v1.z + v2.z + v3.z;
            aw += v0.w + v1.w + v2.w + v3.w;
        }
        for (; j < cnt; j++) {
            int s0 = __shfl_sync(0xffffffffu, my, j);
            float4 v0 = *(const float4*)(feat + (size_t)s0 * D + lane * 4);
            ax += v0.x; ay += v0.y; az += v0.z; aw += v0.w;
        }
    }
    float inv = 1.0f / (float)(d < 1 ? 1 : d);
    float4 r;
    r.x = ax * inv; r.y = ay * inv; r.z = az * inv; r.w = aw * inv;
    *(float4*)(g_agg + (size_t)n * D + lane * 4) = r;
}

// ---------------- fused SAGE layer: out = act(in@Ws + agg@Wn + b) ----------
// 148 blocks x 544 threads; 68 nodes/block; thread computes 4 nodes x 4 cols.
// smem: Ws[128x128], Wn[128x128], A^T[128][68], B^T[128][68]  (~200 KB)
#define LAYER_THREADS 544
#define TILE_N 68
#define SA_STRIDE 68

__global__ void __launch_bounds__(LAYER_THREADS, 1)
k_layer(const float* __restrict__ in, const float* __restrict__ agg,
        const float* __restrict__ Wself, const float* __restrict__ Wneigh,
        const float* __restrict__ bias, float* __restrict__ out, int relu) {
    extern __shared__ float smf[];
    float* sWs = smf;                       // D*D
    float* sWn = sWs + D * D;               // D*D
    float* sA = sWn + D * D;                // D*SA_STRIDE  (A^T: [k][n])
    float* sB = sA + D * SA_STRIDE;         // D*SA_STRIDE

    int tid = threadIdx.x;
    int nb = blockIdx.x * TILE_N;

    // load weights (row-major [k][c]) as float4
    for (int i = tid; i < D * D / 4; i += LAYER_THREADS) {
        ((float4*)sWs)[i] = ((const float4*)Wself)[i];
        ((float4*)sWn)[i] = ((const float4*)Wneigh)[i];
    }
    // load node rows transposed into sA/sB
    for (int idx = tid; idx < TILE_N * 32; idx += LAYER_THREADS) {
        int n = idx >> 5;
        int kq = idx & 31;
        int gn = nb + n;
        float4 va = make_float4(0.f, 0.f, 0.f, 0.f);
        float4 vb = va;
        if (gn < N_NODES) {
            va = *(const float4*)(in + (size_t)gn * D + kq * 4);
            vb = *(const float4*)(agg + (size_t)gn * D + kq * 4);
        }
        sA[(kq * 4 + 0) * SA_STRIDE + n] = va.x;
        sA[(kq * 4 + 1) * SA_STRIDE + n] = va.y;
        sA[(kq * 4 + 2) * SA_STRIDE + n] = va.z;
        sA[(kq * 4 + 3) * SA_STRIDE + n] = va.w;
        sB[(kq * 4 + 0) * SA_STRIDE + n] = vb.x;
        sB[(kq * 4 + 1) * SA_STRIDE + n] = vb.y;
        sB[(kq * 4 + 2) * SA_STRIDE + n] = vb.z;
        sB[(kq * 4 + 3) * SA_STRIDE + n] = vb.w;
    }
    __syncthreads();

    int tx = tid & 31;     // col group: cols 4*tx..4*tx+3
    int ty = tid >> 5;     // node group: nodes 4*ty..4*ty+3 (ty in 0..16)

    float acc[4][4];
#pragma unroll
    for (int i = 0; i < 4; i++)
#pragma unroll
        for (int j = 0; j < 4; j++) acc[i][j] = 0.f;

#pragma unroll 4
    for (int k = 0; k < D; k++) {
        float4 a4 = *(const float4*)(sA + k * SA_STRIDE + 4 * ty);
        float4 b4 = *(const float4*)(sB + k * SA_STRIDE + 4 * ty);
        float4 w4 = *(const float4*)(sWs + k * D + 4 * tx);
        float4 n4 = *(const float4*)(sWn + k * D + 4 * tx);
        float av[4] = {a4.x, a4.y, a4.z, a4.w};
        float bv[4] = {b4.x, b4.y, b4.z, b4.w};
        float wv[4] = {w4.x, w4.y, w4.z, w4.w};
        float nv[4] = {n4.x, n4.y, n4.z, n4.w};
#pragma unroll
        for (int i = 0; i < 4; i++)
#pragma unroll
            for (int j = 0; j < 4; j++)
                acc[i][j] += av[i] * wv[j] + bv[i] * nv[j];
    }

    float4 bq = *(const float4*)(bias + 4 * tx);
    float bb[4] = {bq.x, bq.y, bq.z, bq.w};
#pragma unroll
    for (int i = 0; i < 4; i++) {
        int gn = nb + 4 * ty + i;
        if (gn < N_NODES) {
            float4 o;
            o.x = acc[i][0] + bb[0];
            o.y = acc[i][1] + bb[1];
            o.z = acc[i][2] + bb[2];
            o.w = acc[i][3] + bb[3];
            if (relu) {
                o.x = fmaxf(o.x, 0.f); o.y = fmaxf(o.y, 0.f);
                o.z = fmaxf(o.z, 0.f); o.w = fmaxf(o.w, 0.f);
            }
            *(float4*)(out + (size_t)gn * D + 4 * tx) = o;
        }
    }
}

// ---------------- per-node predictor projections: p = h2 @ [Wtop | Wbot] ---
// one warp per node; 4 dot products of length 128 via warp reduction
__global__ void k_pred(const float* __restrict__ h2, const float* __restrict__ Wp) {
    int gid = blockIdx.x * blockDim.x + threadIdx.x;
    int n = gid >> 5;
    int lane = gid & 31;
    if (n >= N_NODES) return;
    float4 h = *(const float4*)(h2 + (size_t)n * D + lane * 4);
    const float4* W4 = (const float4*)Wp;       // Wp is [256][2] row-major
    float4 wa = W4[2 * lane];                   // rows 4l, 4l+1
    float4 wb = W4[2 * lane + 1];               // rows 4l+2, 4l+3
    float4 wc = W4[64 + 2 * lane];              // rows 128+4l, 128+4l+1
    float4 wd = W4[64 + 2 * lane + 1];
    float p0 = h.x * wa.x + h.y * wa.z + h.z * wb.x + h.w * wb.z;
    float p1 = h.x * wa.y + h.y * wa.w + h.z * wb.y + h.w * wb.w;
    float p2 = h.x * wc.x + h.y * wc.z + h.z * wd.x + h.w * wd.z;
    float p3 = h.x * wc.y + h.y * wc.w + h.z * wd.y + h.w * wd.w;
#pragma unroll
    for (int off = 16; off > 0; off >>= 1) {
        p0 += __shfl_down_sync(0xffffffffu, p0, off);
        p1 += __shfl_down_sync(0xffffffffu, p1, off);
        p2 += __shfl_down_sync(0xffffffffu, p2, off);
        p3 += __shfl_down_sync(0xffffffffu, p3, off);
    }
    if (lane == 0) {
        g_ps[n] = make_float2(p0, p1);
        g_pd[n] = make_float2(p2, p3);
    }
}

// ---------------- edge scores: 4 edges per thread --------------------------
__global__ void k_edge(const int* __restrict__ src, const int* __restrict__ dst,
                       const float* __restrict__ bpred, float* __restrict__ out) {
    int t = blockIdx.x * blockDim.x + threadIdx.x;
    if (t * 4 >= N_EDGES) return;
    float b0 = __ldg(bpred);
    float b1 = __ldg(bpred + 1);
    int4 s = ((const int4*)src)[t];
    int4 d = ((const int4*)dst)[t];
    float2 a0 = g_ps[s.x], a1 = g_ps[s.y], a2 = g_ps[s.z], a3 = g_ps[s.w];
    float2 c0 = g_pd[d.x], c1 = g_pd[d.y], c2 = g_pd[d.z], c3 = g_pd[d.w];
    float4 o0, o1;
    o0.x = a0.x + c0.x + b0; o0.y = a0.y + c0.y + b1;
    o0.z = a1.x + c1.x + b0; o0.w = a1.y + c1.y + b1;
    o1.x = a2.x + c2.x + b0; o1.y = a2.y + c2.y + b1;
    o1.z = a3.x + c3.x + b0; o1.w = a3.y + c3.y + b1;
    ((float4*)out)[t * 2] = o0;
    ((float4*)out)[t * 2 + 1] = o1;
}

// ---------------- launcher -------------------------------------------------
extern "C" void kernel_launch(void* const* d_in, const int* in_sizes, int n_in,
                              void* d_out, int out_size) {
    const float* x = (const float*)d_in[0];
    const int* src = (const int*)d_in[1];
    const int* dst = (const int*)d_in[2];
    const float* Wself1 = (const float*)d_in[3];
    const float* Wneigh1 = (const float*)d_in[4];
    const float* b1 = (const float*)d_in[5];
    const float* Wself2 = (const float*)d_in[6];
    const float* Wneigh2 = (const float*)d_in[7];
    const float* b2 = (const float*)d_in[8];
    const float* Wpred = (const float*)d_in[9];
    const float* bpred = (const float*)d_in[10];
    float* out = (float*)d_out;

    size_t smem_bytes = (size_t)(2 * D * D + 2 * D * SA_STRIDE) * sizeof(float);
    cudaFuncSetAttribute(k_layer, cudaFuncAttributeMaxDynamicSharedMemorySize,
                         (int)smem_bytes);

    float *p_agg, *p_h1, *p_h2;
    void* p_cnt;
    cudaGetSymbolAddress((void**)&p_agg, g_agg);
    cudaGetSymbolAddress((void**)&p_h1, g_h1);
    cudaGetSymbolAddress((void**)&p_h2, g_h2);
    cudaGetSymbolAddress(&p_cnt, g_cnt);

    const int TPB = 256;
    // CSR build: zero counts (memset node), then padded-bucket fill
    cudaMemsetAsync(p_cnt, 0, N_NODES * sizeof(int));
    int fill_blocks = (N_EDGES / 4 + TPB - 1) / TPB;
    k_fill<<<fill_blocks, TPB>>>(src, dst);

    int agg_blocks = (N_NODES * 32 + TPB - 1) / TPB;   // warp per node
    // layer 1
    k_agg<<<agg_blocks, TPB>>>(x);
    k_layer<<<148, LAYER_THREADS, smem_bytes>>>(x, p_agg, Wself1, Wneigh1, b1,
                                                p_h1, 1);
    // layer 2
    k_agg<<<agg_blocks, TPB>>>(p_h1);
    k_layer<<<148, LAYER_THREADS, smem_bytes>>>(p_h1, p_agg, Wself2, Wneigh2, b2,
                                                p_h2, 0);
    // edge predictor (factored through per-node projections)
    k_pred<<<agg_blocks, TPB>>>(p_h2, Wpred);
    k_edge<<<fill_blocks, TPB>>>(src, dst, bpred, out);
}

// round 3
// speedup vs baseline: 1.3882x; 1.1356x over previous
#include <cuda_runtime.h>

#define N_NODES 10000
#define N_EDGES 640000
#define D 128
#define CAP 160   // padded CSR bucket capacity (mean deg 64, sigma 8)

// ---------------- scratch (device globals; no allocation allowed) ----------
__device__ float g_agg[N_NODES * D];
__device__ float g_h1[N_NODES * D];
__device__ float4 g_vself[N_NODES];   // (v·A1 , v·A3) self terms
__device__ float4 g_vnb[N_NODES];     // (v·A2 , v·A4) neighbor terms
__device__ float2 g_ps[N_NODES];
__device__ float2 g_pd[N_NODES];
__device__ float g_wc[D * 8];         // [A1|A2|A3|A4] columns
__device__ float g_c[4];              // b2@Wp_top, b2@Wp_bot
__device__ int g_cnt[N_NODES];
__device__ int g_csr[N_NODES * CAP];

// ---------------- padded CSR fill: 4 edges per thread ----------------------
__global__ void k_fill(const int* __restrict__ src, const int* __restrict__ dst) {
    int t = blockIdx.x * blockDim.x + threadIdx.x;
    if (t * 4 >= N_EDGES) return;
    int4 s = ((const int4*)src)[t];
    int4 d = ((const int4*)dst)[t];
    int p0 = atomicAdd(&g_cnt[d.x], 1);
    int p1 = atomicAdd(&g_cnt[d.y], 1);
    int p2 = atomicAdd(&g_cnt[d.z], 1);
    int p3 = atomicAdd(&g_cnt[d.w], 1);
    if (p0 < CAP) g_csr[d.x * CAP + p0] = s.x;
    if (p1 < CAP) g_csr[d.y * CAP + p1] = s.y;
    if (p2 < CAP) g_csr[d.z * CAP + p2] = s.z;
    if (p3 < CAP) g_csr[d.w * CAP + p3] = s.w;
}

// ---------------- folded predictor weights: Wc = [Ws2|Wn2]@[Wp_top;Wp_bot] -
// one block of 128 threads; thread k computes row k of Wc (8 values)
__global__ void k_wc(const float* __restrict__ Ws2, const float* __restrict__ Wn2,
                     const float* __restrict__ b2, const float* __restrict__ Wp) {
    __shared__ float sWp[256 * 2];
    int t = threadIdx.x;
    for (int i = t; i < 512; i += 128) sWp[i] = Wp[i];
    __syncthreads();
    float a[8] = {0, 0, 0, 0, 0, 0, 0, 0};
#pragma unroll 4
    for (int j = 0; j < D; j++) {
        float ws = Ws2[t * D + j];
        float wn = Wn2[t * D + j];
        float p0 = sWp[j * 2], p1 = sWp[j * 2 + 1];
        float q0 = sWp[(128 + j) * 2], q1 = sWp[(128 + j) * 2 + 1];
        a[0] += ws * p0; a[1] += ws * p1;   // A1
        a[2] += wn * p0; a[3] += wn * p1;   // A2
        a[4] += ws * q0; a[5] += ws * q1;   // A3
        a[6] += wn * q0; a[7] += wn * q1;   // A4
    }
#pragma unroll
    for (int j = 0; j < 8; j++) g_wc[t * 8 + j] = a[j];
    if (t < 4) {  // consts: c[0..1]=b2@Wp_top, c[2..3]=b2@Wp_bot
        int half = t >> 1, c = t & 1;
        float s = 0.f;
        for (int j = 0; j < D; j++) s += b2[j] * sWp[(half * 128 + j) * 2 + c];
        g_c[t] = s;
    }
}

// ---------------- pull-based mean aggregation (full 128-d, layer 1) --------
__global__ void k_agg(const float* __restrict__ feat) {
    int gid = blockIdx.x * blockDim.x + threadIdx.x;
    int n = gid >> 5;
    int lane = gid & 31;
    if (n >= N_NODES) return;
    int beg = n * CAP;
    int d = g_cnt[n];
    float ax = 0.f, ay = 0.f, az = 0.f, aw = 0.f;
    for (int base = 0; base < d; base += 32) {
        int my = -1;
        if (base + lane < d) my = g_csr[beg + base + lane];
        int cnt = min(32, d - base);
        int j = 0;
        for (; j + 4 <= cnt; j += 4) {
            int s0 = __shfl_sync(0xffffffffu, my, j);
            int s1 = __shfl_sync(0xffffffffu, my, j + 1);
            int s2 = __shfl_sync(0xffffffffu, my, j + 2);
            int s3 = __shfl_sync(0xffffffffu, my, j + 3);
            float4 v0 = *(const float4*)(feat + (size_t)s0 * D + lane * 4);
            float4 v1 = *(const float4*)(feat + (size_t)s1 * D + lane * 4);
            float4 v2 = *(const float4*)(feat + (size_t)s2 * D + lane * 4);
            float4 v3 = *(const float4*)(feat + (size_t)s3 * D + lane * 4);
            ax += v0.x + v1.x + v2.x + v3.x;
            ay += v0.y + v1.y + v2.y + v3.y;
            az += v0.z + v1.z + v2.z + v3.z;
            aw += v0.w + v1.w + v2.w + v3.w;
        }
        for (; j < cnt; j++) {
            int s0 = __shfl_sync(0xffffffffu, my, j);
            float4 v0 = *(const float4*)(feat + (size_t)s0 * D + lane * 4);
            ax += v0.x; ay += v0.y; az += v0.z; aw += v0.w;
        }
    }
    float inv = 1.0f / (float)(d < 1 ? 1 : d);
    float4 r;
    r.x = ax * inv; r.y = ay * inv; r.z = az * inv; r.w = aw * inv;
    *(float4*)(g_agg + (size_t)n * D + lane * 4) = r;
}

// ---------------- fused SAGE layer 1: h1 = relu(x@Ws + agg@Wn + b) ---------
#define LAYER_THREADS 544
#define TILE_N 68
#define SA_STRIDE 68

__global__ void __launch_bounds__(LAYER_THREADS, 1)
k_layer(const float* __restrict__ in, const float* __restrict__ agg,
        const float* __restrict__ Wself, const float* __restrict__ Wneigh,
        const float* __restrict__ bias, float* __restrict__ out) {
    extern __shared__ float smf[];
    float* sWs = smf;
    float* sWn = sWs + D * D;
    float* sA = sWn + D * D;
    float* sB = sA + D * SA_STRIDE;

    int tid = threadIdx.x;
    int nb = blockIdx.x * TILE_N;

    for (int i = tid; i < D * D / 4; i += LAYER_THREADS) {
        ((float4*)sWs)[i] = ((const float4*)Wself)[i];
        ((float4*)sWn)[i] = ((const float4*)Wneigh)[i];
    }
    for (int idx = tid; idx < TILE_N * 32; idx += LAYER_THREADS) {
        int n = idx >> 5;
        int kq = idx & 31;
        int gn = nb + n;
        float4 va = make_float4(0.f, 0.f, 0.f, 0.f);
        float4 vb = va;
        if (gn < N_NODES) {
            va = *(const float4*)(in + (size_t)gn * D + kq * 4);
            vb = *(const float4*)(agg + (size_t)gn * D + kq * 4);
        }
        sA[(kq * 4 + 0) * SA_STRIDE + n] = va.x;
        sA[(kq * 4 + 1) * SA_STRIDE + n] = va.y;
        sA[(kq * 4 + 2) * SA_STRIDE + n] = va.z;
        sA[(kq * 4 + 3) * SA_STRIDE + n] = va.w;
        sB[(kq * 4 + 0) * SA_STRIDE + n] = vb.x;
        sB[(kq * 4 + 1) * SA_STRIDE + n] = vb.y;
        sB[(kq * 4 + 2) * SA_STRIDE + n] = vb.z;
        sB[(kq * 4 + 3) * SA_STRIDE + n] = vb.w;
    }
    __syncthreads();

    int tx = tid & 31;
    int ty = tid >> 5;

    float acc[4][4];
#pragma unroll
    for (int i = 0; i < 4; i++)
#pragma unroll
        for (int j = 0; j < 4; j++) acc[i][j] = 0.f;

#pragma unroll 4
    for (int k = 0; k < D; k++) {
        float4 a4 = *(const float4*)(sA + k * SA_STRIDE + 4 * ty);
        float4 b4 = *(const float4*)(sB + k * SA_STRIDE + 4 * ty);
        float4 w4 = *(const float4*)(sWs + k * D + 4 * tx);
        float4 n4 = *(const float4*)(sWn + k * D + 4 * tx);
        float av[4] = {a4.x, a4.y, a4.z, a4.w};
        float bv[4] = {b4.x, b4.y, b4.z, b4.w};
        float wv[4] = {w4.x, w4.y, w4.z, w4.w};
        float nv[4] = {n4.x, n4.y, n4.z, n4.w};
#pragma unroll
        for (int i = 0; i < 4; i++)
#pragma unroll
            for (int j = 0; j < 4; j++)
                acc[i][j] += av[i] * wv[j] + bv[i] * nv[j];
    }

    float4 bq = *(const float4*)(bias + 4 * tx);
    float bb[4] = {bq.x, bq.y, bq.z, bq.w};
#pragma unroll
    for (int i = 0; i < 4; i++) {
        int gn = nb + 4 * ty + i;
        if (gn < N_NODES) {
            float4 o;
            o.x = fmaxf(acc[i][0] + bb[0], 0.f);
            o.y = fmaxf(acc[i][1] + bb[1], 0.f);
            o.z = fmaxf(acc[i][2] + bb[2], 0.f);
            o.w = fmaxf(acc[i][3] + bb[3], 0.f);
            *(float4*)(out + (size_t)gn * D + 4 * tx) = o;
        }
    }
}

// ---------------- project h1 -> 8 dims: v = h1 @ Wc ------------------------
// one warp per node; lane owns k = 4*lane .. 4*lane+3
__global__ void k_proj(const float* __restrict__ h1) {
    int gid = blockIdx.x * blockDim.x + threadIdx.x;
    int n = gid >> 5;
    int lane = gid & 31;
    if (n >= N_NODES) return;
    float4 h = *(const float4*)(h1 + (size_t)n * D + lane * 4);
    float hv[4] = {h.x, h.y, h.z, h.w};
    float a[8] = {0, 0, 0, 0, 0, 0, 0, 0};
#pragma unroll
    for (int r = 0; r < 4; r++) {
        const float4* w = (const float4*)(g_wc + (4 * lane + r) * 8);
        float4 w0 = w[0], w1 = w[1];
        a[0] += hv[r] * w0.x; a[1] += hv[r] * w0.y;
        a[2] += hv[r] * w0.z; a[3] += hv[r] * w0.w;
        a[4] += hv[r] * w1.x; a[5] += hv[r] * w1.y;
        a[6] += hv[r] * w1.z; a[7] += hv[r] * w1.w;
    }
#pragma unroll
    for (int off = 16; off > 0; off >>= 1) {
#pragma unroll
        for (int j = 0; j < 8; j++)
            a[j] += __shfl_down_sync(0xffffffffu, a[j], off);
    }
    if (lane == 0) {
        g_vself[n] = make_float4(a[0], a[1], a[4], a[5]);
        g_vnb[n] = make_float4(a[2], a[3], a[6], a[7]);
    }
}

// ---------------- tiny aggregation over 4-float projections ----------------
// one warp per node; lanes stride over neighbors
__global__ void k_agg2() {
    int gid = blockIdx.x * blockDim.x + threadIdx.x;
    int n = gid >> 5;
    int lane = gid & 31;
    if (n >= N_NODES) return;
    int beg = n * CAP;
    int d = g_cnt[n];
    float ax = 0.f, ay = 0.f, az = 0.f, aw = 0.f;
    for (int i = lane; i < d; i += 32) {
        int s = g_csr[beg + i];
        float4 v = g_vnb[s];
        ax += v.x; ay += v.y; az += v.z; aw += v.w;
    }
#pragma unroll
    for (int off = 16; off > 0; off >>= 1) {
        ax += __shfl_down_sync(0xffffffffu, ax, off);
        ay += __shfl_down_sync(0xffffffffu, ay, off);
        az += __shfl_down_sync(0xffffffffu, az, off);
        aw += __shfl_down_sync(0xffffffffu, aw, off);
    }
    if (lane == 0) {
        float inv = 1.0f / (float)(d < 1 ? 1 : d);
        float4 vs = g_vself[n];
        g_ps[n] = make_float2(vs.x + ax * inv, vs.y + ay * inv);
        g_pd[n] = make_float2(vs.z + az * inv, vs.w + aw * inv);
    }
}

// ---------------- edge scores: 4 edges per thread --------------------------
__global__ void k_edge(const int* __restrict__ src, const int* __restrict__ dst,
                       const float* __restrict__ bpred, float* __restrict__ out) {
    int t = blockIdx.x * blockDim.x + threadIdx.x;
    if (t * 4 >= N_EDGES) return;
    float b0 = __ldg(bpred) + g_c[0] + g_c[2];
    float b1 = __ldg(bpred + 1) + g_c[1] + g_c[3];
    int4 s = ((const int4*)src)[t];
    int4 d = ((const int4*)dst)[t];
    float2 a0 = g_ps[s.x], a1 = g_ps[s.y], a2 = g_ps[s.z], a3 = g_ps[s.w];
    float2 c0 = g_pd[d.x], c1 = g_pd[d.y], c2 = g_pd[d.z], c3 = g_pd[d.w];
    float4 o0, o1;
    o0.x = a0.x + c0.x + b0; o0.y = a0.y + c0.y + b1;
    o0.z = a1.x + c1.x + b0; o0.w = a1.y + c1.y + b1;
    o1.x = a2.x + c2.x + b0; o1.y = a2.y + c2.y + b1;
    o1.z = a3.x + c3.x + b0; o1.w = a3.y + c3.y + b1;
    ((float4*)out)[t * 2] = o0;
    ((float4*)out)[t * 2 + 1] = o1;
}

// ---------------- launcher -------------------------------------------------
extern "C" void kernel_launch(void* const* d_in, const int* in_sizes, int n_in,
                              void* d_out, int out_size) {
    const float* x = (const float*)d_in[0];
    const int* src = (const int*)d_in[1];
    const int* dst = (const int*)d_in[2];
    const float* Wself1 = (const float*)d_in[3];
    const float* Wneigh1 = (const float*)d_in[4];
    const float* b1 = (const float*)d_in[5];
    const float* Wself2 = (const float*)d_in[6];
    const float* Wneigh2 = (const float*)d_in[7];
    const float* b2 = (const float*)d_in[8];
    const float* Wpred = (const float*)d_in[9];
    const float* bpred = (const float*)d_in[10];
    float* out = (float*)d_out;

    size_t smem_bytes = (size_t)(2 * D * D + 2 * D * SA_STRIDE) * sizeof(float);
    cudaFuncSetAttribute(k_layer, cudaFuncAttributeMaxDynamicSharedMemorySize,
                         (int)smem_bytes);

    float *p_agg, *p_h1;
    void* p_cnt;
    cudaGetSymbolAddress((void**)&p_agg, g_agg);
    cudaGetSymbolAddress((void**)&p_h1, g_h1);
    cudaGetSymbolAddress(&p_cnt, g_cnt);

    const int TPB = 256;
    int fill_blocks = (N_EDGES / 4 + TPB - 1) / TPB;
    int warp_blocks = (N_NODES * 32 + TPB - 1) / TPB;

    cudaMemsetAsync(p_cnt, 0, N_NODES * sizeof(int));
    k_fill<<<fill_blocks, TPB>>>(src, dst);
    k_wc<<<1, 128>>>(Wself2, Wneigh2, b2, Wpred);

    k_agg<<<warp_blocks, TPB>>>(x);
    k_layer<<<148, LAYER_THREADS, smem_bytes>>>(x, p_agg, Wself1, Wneigh1, b1,
                                                p_h1);
    k_proj<<<warp_blocks, TPB>>>(p_h1);
    k_agg2<<<warp_blocks, TPB>>>();
    k_edge<<<fill_blocks, TPB>>>(src, dst, bpred, out);
}

// round 4
// speedup vs baseline: 1.6381x; 1.1800x over previous
#include <cuda_runtime.h>
#include <cuda_bf16.h>

#define N_NODES 10000
#define N_EDGES 640000
#define D 128
#define CAP 160   // padded CSR bucket capacity (mean deg 64, sigma 8)

#define FILL_BLOCKS 625      // 640000/4/256
#define CVT_BLOCKS 1250      // 10000*32/256

// ---------------- scratch (device globals; no allocation allowed) ----------
__device__ float g_agg[N_NODES * D];
__device__ uint2 g_xh[N_NODES * 32];  // x in packed bf16 (row = 32 x uint2)
__device__ float4 g_vself[N_NODES];   // (A1 , A3) self terms
__device__ float4 g_vnb[N_NODES];     // (A2 , A4) neighbor terms
__device__ float2 g_ps[N_NODES];
__device__ float2 g_pd[N_NODES];
__device__ float g_wc[D * 8];         // [A1|A2|A3|A4] rows
__device__ float g_c[4];              // b2@Wp_top, b2@Wp_bot
__device__ int g_cnt[N_NODES];
__device__ int g_csr[N_NODES * CAP];

// ---------------- fused prep: CSR fill + bf16 convert + weight fold --------
__global__ void k_prep(const int* __restrict__ src, const int* __restrict__ dst,
                       const float* __restrict__ x,
                       const float* __restrict__ Ws2, const float* __restrict__ Wn2,
                       const float* __restrict__ b2, const float* __restrict__ Wp) {
    __shared__ float sWp[256 * 2];
    int b = blockIdx.x;
    int tid = threadIdx.x;
    if (b < FILL_BLOCKS) {
        int t = b * 256 + tid;
        if (t * 4 >= N_EDGES) return;
        int4 s = ((const int4*)src)[t];
        int4 d = ((const int4*)dst)[t];
        int p0 = atomicAdd(&g_cnt[d.x], 1);
        int p1 = atomicAdd(&g_cnt[d.y], 1);
        int p2 = atomicAdd(&g_cnt[d.z], 1);
        int p3 = atomicAdd(&g_cnt[d.w], 1);
        if (p0 < CAP) g_csr[d.x * CAP + p0] = s.x;
        if (p1 < CAP) g_csr[d.y * CAP + p1] = s.y;
        if (p2 < CAP) g_csr[d.z * CAP + p2] = s.z;
        if (p3 < CAP) g_csr[d.w * CAP + p3] = s.w;
    } else if (b < FILL_BLOCKS + CVT_BLOCKS) {
        int idx = (b - FILL_BLOCKS) * 256 + tid;
        if (idx >= N_NODES * 32) return;
        float4 v = ((const float4*)x)[idx];
        __nv_bfloat162 q0 = __floats2bfloat162_rn(v.x, v.y);
        __nv_bfloat162 q1 = __floats2bfloat162_rn(v.z, v.w);
        uint2 u;
        u.x = *reinterpret_cast<unsigned*>(&q0);
        u.y = *reinterpret_cast<unsigned*>(&q1);
        g_xh[idx] = u;
    } else {
        // weight fold: Wc = [Ws2|Wn2] @ [Wp_top ; Wp_bot], consts from b2
        for (int i = tid; i < 512; i += 256) sWp[i] = Wp[i];
        __syncthreads();
        int t = tid;
        if (t < 128) {
            float a[8] = {0, 0, 0, 0, 0, 0, 0, 0};
#pragma unroll 4
            for (int j = 0; j < D; j++) {
                float ws = Ws2[t * D + j];
                float wn = Wn2[t * D + j];
                float p0 = sWp[j * 2], p1 = sWp[j * 2 + 1];
                float q0 = sWp[(128 + j) * 2], q1 = sWp[(128 + j) * 2 + 1];
                a[0] += ws * p0; a[1] += ws * p1;   // A1
                a[2] += wn * p0; a[3] += wn * p1;   // A2
                a[4] += ws * q0; a[5] += ws * q1;   // A3
                a[6] += wn * q0; a[7] += wn * q1;   // A4
            }
#pragma unroll
            for (int j = 0; j < 8; j++) g_wc[t * 8 + j] = a[j];
        }
        if (t < 4) {
            int half = t >> 1, c = t & 1;
            float s = 0.f;
            for (int j = 0; j < D; j++) s += b2[j] * sWp[(half * 128 + j) * 2 + c];
            g_c[t] = s;
        }
    }
}

// ---------------- pull-based mean aggregation over bf16 x ------------------
// one warp per node; lane l owns feature chunk [4l, 4l+4)
__global__ void k_agg(const float* __restrict__ unused) {
    int gid = blockIdx.x * blockDim.x + threadIdx.x;
    int n = gid >> 5;
    int lane = gid & 31;
    if (n >= N_NODES) return;
    int beg = n * CAP;
    int d = g_cnt[n];
    float ax = 0.f, ay = 0.f, az = 0.f, aw = 0.f;
    for (int base = 0; base < d; base += 32) {
        int my = -1;
        if (base + lane < d) my = g_csr[beg + base + lane];
        int cnt = min(32, d - base);
        int j = 0;
        for (; j + 4 <= cnt; j += 4) {
            int s0 = __shfl_sync(0xffffffffu, my, j);
            int s1 = __shfl_sync(0xffffffffu, my, j + 1);
            int s2 = __shfl_sync(0xffffffffu, my, j + 2);
            int s3 = __shfl_sync(0xffffffffu, my, j + 3);
            uint2 u0 = g_xh[s0 * 32 + lane];
            uint2 u1 = g_xh[s1 * 32 + lane];
            uint2 u2 = g_xh[s2 * 32 + lane];
            uint2 u3 = g_xh[s3 * 32 + lane];
            float2 f;
            f = __bfloat1622float2(*reinterpret_cast<__nv_bfloat162*>(&u0.x));
            ax += f.x; ay += f.y;
            f = __bfloat1622float2(*reinterpret_cast<__nv_bfloat162*>(&u0.y));
            az += f.x; aw += f.y;
            f = __bfloat1622float2(*reinterpret_cast<__nv_bfloat162*>(&u1.x));
            ax += f.x; ay += f.y;
            f = __bfloat1622float2(*reinterpret_cast<__nv_bfloat162*>(&u1.y));
            az += f.x; aw += f.y;
            f = __bfloat1622float2(*reinterpret_cast<__nv_bfloat162*>(&u2.x));
            ax += f.x; ay += f.y;
            f = __bfloat1622float2(*reinterpret_cast<__nv_bfloat162*>(&u2.y));
            az += f.x; aw += f.y;
            f = __bfloat1622float2(*reinterpret_cast<__nv_bfloat162*>(&u3.x));
            ax += f.x; ay += f.y;
            f = __bfloat1622float2(*reinterpret_cast<__nv_bfloat162*>(&u3.y));
            az += f.x; aw += f.y;
        }
        for (; j < cnt; j++) {
            int s0 = __shfl_sync(0xffffffffu, my, j);
            uint2 u0 = g_xh[s0 * 32 + lane];
            float2 f;
            f = __bfloat1622float2(*reinterpret_cast<__nv_bfloat162*>(&u0.x));
            ax += f.x; ay += f.y;
            f = __bfloat1622float2(*reinterpret_cast<__nv_bfloat162*>(&u0.y));
            az += f.x; aw += f.y;
        }
    }
    float inv = 1.0f / (float)(d < 1 ? 1 : d);
    float4 r;
    r.x = ax * inv; r.y = ay * inv; r.z = az * inv; r.w = aw * inv;
    *(float4*)(g_agg + (size_t)n * D + lane * 4) = r;
}

// ------- fused SAGE layer 1 + projection: v = relu(x@Ws+agg@Wn+b) @ Wc -----
#define LAYER_THREADS 544
#define TILE_N 68
#define SA_STRIDE 68

__global__ void __launch_bounds__(LAYER_THREADS, 1)
k_layer(const float* __restrict__ in, const float* __restrict__ agg,
        const float* __restrict__ Wself, const float* __restrict__ Wneigh,
        const float* __restrict__ bias) {
    extern __shared__ float smf[];
    float* sWs = smf;                       // D*D
    float* sWn = sWs + D * D;               // D*D
    float* sA = sWn + D * D;                // D*SA_STRIDE
    float* sB = sA + D * SA_STRIDE;         // D*SA_STRIDE
    float* sWc = sB + D * SA_STRIDE;        // D*8

    int tid = threadIdx.x;
    int nb = blockIdx.x * TILE_N;

    for (int i = tid; i < D * D / 4; i += LAYER_THREADS) {
        ((float4*)sWs)[i] = ((const float4*)Wself)[i];
        ((float4*)sWn)[i] = ((const float4*)Wneigh)[i];
    }
    for (int i = tid; i < D * 2; i += LAYER_THREADS)
        ((float4*)sWc)[i] = ((const float4*)g_wc)[i];
    for (int idx = tid; idx < TILE_N * 32; idx += LAYER_THREADS) {
        int n = idx >> 5;
        int kq = idx & 31;
        int gn = nb + n;
        float4 va = make_float4(0.f, 0.f, 0.f, 0.f);
        float4 vb = va;
        if (gn < N_NODES) {
            va = *(const float4*)(in + (size_t)gn * D + kq * 4);
            vb = *(const float4*)(agg + (size_t)gn * D + kq * 4);
        }
        sA[(kq * 4 + 0) * SA_STRIDE + n] = va.x;
        sA[(kq * 4 + 1) * SA_STRIDE + n] = va.y;
        sA[(kq * 4 + 2) * SA_STRIDE + n] = va.z;
        sA[(kq * 4 + 3) * SA_STRIDE + n] = va.w;
        sB[(kq * 4 + 0) * SA_STRIDE + n] = vb.x;
        sB[(kq * 4 + 1) * SA_STRIDE + n] = vb.y;
        sB[(kq * 4 + 2) * SA_STRIDE + n] = vb.z;
        sB[(kq * 4 + 3) * SA_STRIDE + n] = vb.w;
    }
    __syncthreads();

    int tx = tid & 31;     // col group: cols 4*tx..4*tx+3 (== lane id)
    int ty = tid >> 5;     // node group: nodes 4*ty..4*ty+3

    float acc[4][4];
#pragma unroll
    for (int i = 0; i < 4; i++)
#pragma unroll
        for (int j = 0; j < 4; j++) acc[i][j] = 0.f;

#pragma unroll 4
    for (int k = 0; k < D; k++) {
        float4 a4 = *(const float4*)(sA + k * SA_STRIDE + 4 * ty);
        float4 b4 = *(const float4*)(sB + k * SA_STRIDE + 4 * ty);
        float4 w4 = *(const float4*)(sWs + k * D + 4 * tx);
        float4 n4 = *(const float4*)(sWn + k * D + 4 * tx);
        float av[4] = {a4.x, a4.y, a4.z, a4.w};
        float bv[4] = {b4.x, b4.y, b4.z, b4.w};
        float wv[4] = {w4.x, w4.y, w4.z, w4.w};
        float nv[4] = {n4.x, n4.y, n4.z, n4.w};
#pragma unroll
        for (int i = 0; i < 4; i++)
#pragma unroll
            for (int j = 0; j < 4; j++)
                acc[i][j] += av[i] * wv[j] + bv[i] * nv[j];
    }

    // epilogue: bias + relu, then project 128 cols -> 8 dims through sWc
    float4 bq = *(const float4*)(bias + 4 * tx);
    float bb[4] = {bq.x, bq.y, bq.z, bq.w};
    float pv[4][8];
#pragma unroll
    for (int i = 0; i < 4; i++)
#pragma unroll
        for (int m = 0; m < 8; m++) pv[i][m] = 0.f;

#pragma unroll
    for (int j = 0; j < 4; j++) {
        int c = 4 * tx + j;
        float4 wc0 = *(const float4*)(sWc + c * 8);
        float4 wc1 = *(const float4*)(sWc + c * 8 + 4);
        float wcv[8] = {wc0.x, wc0.y, wc0.z, wc0.w, wc1.x, wc1.y, wc1.z, wc1.w};
#pragma unroll
        for (int i = 0; i < 4; i++) {
            float h = fmaxf(acc[i][j] + bb[j], 0.f);
#pragma unroll
            for (int m = 0; m < 8; m++) pv[i][m] += h * wcv[m];
        }
    }
    // butterfly reduce across the 32 lanes (threads sharing ty = one warp)
#pragma unroll
    for (int off = 16; off > 0; off >>= 1) {
#pragma unroll
        for (int i = 0; i < 4; i++)
#pragma unroll
            for (int m = 0; m < 8; m++)
                pv[i][m] += __shfl_xor_sync(0xffffffffu, pv[i][m], off);
    }
    // lane l writes entry (i = l>>3, m = l&7) of node nb + 4*ty + i
    int i = tx >> 3, m = tx & 7;
    int gn = nb + 4 * ty + i;
    if (gn < N_NODES) {
        float val = pv[i][m];
        int sel = (m >> 1) & 1;                 // 0 -> vself, 1 -> vnb
        int pos = (m & 1) + ((m >> 2) << 1);
        float* basep = sel ? (float*)&g_vnb[gn] : (float*)&g_vself[gn];
        basep[pos] = val;
    }
}

// ---------------- tiny aggregation over 4-float projections ----------------
__global__ void k_agg2() {
    int gid = blockIdx.x * blockDim.x + threadIdx.x;
    int n = gid >> 5;
    int lane = gid & 31;
    if (n >= N_NODES) return;
    int beg = n * CAP;
    int d = g_cnt[n];
    float ax = 0.f, ay = 0.f, az = 0.f, aw = 0.f;
    for (int i = lane; i < d; i += 32) {
        int s = g_csr[beg + i];
        float4 v = g_vnb[s];
        ax += v.x; ay += v.y; az += v.z; aw += v.w;
    }
#pragma unroll
    for (int off = 16; off > 0; off >>= 1) {
        ax += __shfl_down_sync(0xffffffffu, ax, off);
        ay += __shfl_down_sync(0xffffffffu, ay, off);
        az += __shfl_down_sync(0xffffffffu, az, off);
        aw += __shfl_down_sync(0xffffffffu, aw, off);
    }
    if (lane == 0) {
        float inv = 1.0f / (float)(d < 1 ? 1 : d);
        float4 vs = g_vself[n];
        g_ps[n] = make_float2(vs.x + ax * inv, vs.y + ay * inv);
        g_pd[n] = make_float2(vs.z + az * inv, vs.w + aw * inv);
    }
}

// ---------------- edge scores: 4 edges per thread --------------------------
__global__ void k_edge(const int* __restrict__ src, const int* __restrict__ dst,
                       const float* __restrict__ bpred, float* __restrict__ out) {
    int t = blockIdx.x * blockDim.x + threadIdx.x;
    if (t * 4 >= N_EDGES) return;
    float b0 = __ldg(bpred) + g_c[0] + g_c[2];
    float b1 = __ldg(bpred + 1) + g_c[1] + g_c[3];
    int4 s = ((const int4*)src)[t];
    int4 d = ((const int4*)dst)[t];
    float2 a0 = g_ps[s.x], a1 = g_ps[s.y], a2 = g_ps[s.z], a3 = g_ps[s.w];
    float2 c0 = g_pd[d.x], c1 = g_pd[d.y], c2 = g_pd[d.z], c3 = g_pd[d.w];
    float4 o0, o1;
    o0.x = a0.x + c0.x + b0; o0.y = a0.y + c0.y + b1;
    o0.z = a1.x + c1.x + b0; o0.w = a1.y + c1.y + b1;
    o1.x = a2.x + c2.x + b0; o1.y = a2.y + c2.y + b1;
    o1.z = a3.x + c3.x + b0; o1.w = a3.y + c3.y + b1;
    ((float4*)out)[t * 2] = o0;
    ((float4*)out)[t * 2 + 1] = o1;
}

// ---------------- launcher -------------------------------------------------
extern "C" void kernel_launch(void* const* d_in, const int* in_sizes, int n_in,
                              void* d_out, int out_size) {
    const float* x = (const float*)d_in[0];
    const int* src = (const int*)d_in[1];
    const int* dst = (const int*)d_in[2];
    const float* Wself1 = (const float*)d_in[3];
    const float* Wneigh1 = (const float*)d_in[4];
    const float* b1 = (const float*)d_in[5];
    const float* Wself2 = (const float*)d_in[6];
    const float* Wneigh2 = (const float*)d_in[7];
    const float* b2 = (const float*)d_in[8];
    const float* Wpred = (const float*)d_in[9];
    const float* bpred = (const float*)d_in[10];
    float* out = (float*)d_out;

    size_t smem_bytes =
        (size_t)(2 * D * D + 2 * D * SA_STRIDE + D * 8) * sizeof(float);
    cudaFuncSetAttribute(k_layer, cudaFuncAttributeMaxDynamicSharedMemorySize,
                         (int)smem_bytes);

    float* p_agg;
    void* p_cnt;
    cudaGetSymbolAddress((void**)&p_agg, g_agg);
    cudaGetSymbolAddress(&p_cnt, g_cnt);

    const int TPB = 256;
    int warp_blocks = (N_NODES * 32 + TPB - 1) / TPB;

    cudaMemsetAsync(p_cnt, 0, N_NODES * sizeof(int));
    k_prep<<<FILL_BLOCKS + CVT_BLOCKS + 1, TPB>>>(src, dst, x, Wself2, Wneigh2,
                                                  b2, Wpred);
    k_agg<<<warp_blocks, TPB>>>(x);
    k_layer<<<148, LAYER_THREADS, smem_bytes>>>(x, p_agg, Wself1, Wneigh1, b1);
    k_agg2<<<warp_blocks, TPB>>>();
    k_edge<<<(N_EDGES / 4 + TPB - 1) / TPB, TPB>>>(src, dst, bpred, out);
}

// round 6
// speedup vs baseline: 1.8615x; 1.1364x over previous
#include <cuda_runtime.h>
#include <cuda_bf16.h>
#include <cstdint>

#define N_NODES 10000
#define N_EDGES 640000
#define D 128
#define CAP 160            // padded CSR bucket capacity (mean deg 64, sigma 8)
#define FILL_BLOCKS 313    // ceil(640000/8/256)
#define CVT_BLOCKS 1250    // 10000*32/256
#define GEMM_BLOCKS 79     // ceil(10000/128)

// ---------------- scratch (device globals; no allocation allowed) ----------
__device__ float g_agg[N_NODES * D];
__device__ uint2 g_xh[N_NODES * 32];  // x in packed bf16
__device__ float4 g_vself[N_NODES];   // (A1 , A3) self terms
__device__ float4 g_vnb[N_NODES];     // (A2 , A4) neighbor terms
__device__ float2 g_ps[N_NODES];
__device__ float2 g_pd[N_NODES];
__device__ float g_wc[D * 8];         // [A1|A2|A3|A4] rows
__device__ float g_c[4];
__device__ int g_cnt[N_NODES];        // zeroed at end of k_agg2 (replay invariant)
__device__ int g_csr[N_NODES * CAP];

// ---------------- helpers ---------------------------------------------------
__device__ __forceinline__ uint32_t f2tf32(float v) {
    uint32_t t;
    asm("cvt.rna.tf32.f32 %0, %1;" : "=r"(t) : "f"(v));
    return t;
}
__device__ __forceinline__ void mma_tf32(float* c, const uint32_t* a,
                                         uint32_t b0, uint32_t b1) {
    asm volatile(
        "mma.sync.aligned.m16n8k8.row.col.f32.tf32.tf32.f32 "
        "{%0,%1,%2,%3}, {%4,%5,%6,%7}, {%8,%9}, {%0,%1,%2,%3};"
        : "+f"(c[0]), "+f"(c[1]), "+f"(c[2]), "+f"(c[3])
        : "r"(a[0]), "r"(a[1]), "r"(a[2]), "r"(a[3]), "r"(b0), "r"(b1));
}

// ---------------- fused prep: CSR fill + bf16 convert + weight fold --------
__global__ void k_prep(const int* __restrict__ src, const int* __restrict__ dst,
                       const float* __restrict__ x,
                       const float* __restrict__ Ws2,
                       const float* __restrict__ Wn2,
                       const float* __restrict__ b2,
                       const float* __restrict__ Wp) {
    __shared__ float sWp[256 * 2];
    int b = blockIdx.x;
    int tid = threadIdx.x;
    if (b < FILL_BLOCKS) {
        int t = b * 256 + tid;
        if (t * 8 >= N_EDGES) return;
        int4 s0 = ((const int4*)src)[2 * t], s1 = ((const int4*)src)[2 * t + 1];
        int4 d0 = ((const int4*)dst)[2 * t], d1 = ((const int4*)dst)[2 * t + 1];
        int p0 = atomicAdd(&g_cnt[d0.x], 1);
        int p1 = atomicAdd(&g_cnt[d0.y], 1);
        int p2 = atomicAdd(&g_cnt[d0.z], 1);
        int p3 = atomicAdd(&g_cnt[d0.w], 1);
        int p4 = atomicAdd(&g_cnt[d1.x], 1);
        int p5 = atomicAdd(&g_cnt[d1.y], 1);
        int p6 = atomicAdd(&g_cnt[d1.z], 1);
        int p7 = atomicAdd(&g_cnt[d1.w], 1);
        if (p0 < CAP) g_csr[d0.x * CAP + p0] = s0.x;
        if (p1 < CAP) g_csr[d0.y * CAP + p1] = s0.y;
        if (p2 < CAP) g_csr[d0.z * CAP + p2] = s0.z;
        if (p3 < CAP) g_csr[d0.w * CAP + p3] = s0.w;
        if (p4 < CAP) g_csr[d1.x * CAP + p4] = s1.x;
        if (p5 < CAP) g_csr[d1.y * CAP + p5] = s1.y;
        if (p6 < CAP) g_csr[d1.z * CAP + p6] = s1.z;
        if (p7 < CAP) g_csr[d1.w * CAP + p7] = s1.w;
    } else if (b < FILL_BLOCKS + CVT_BLOCKS) {
        int idx = (b - FILL_BLOCKS) * 256 + tid;
        if (idx >= N_NODES * 32) return;
        float4 v = ((const float4*)x)[idx];
        __nv_bfloat162 q0 = __floats2bfloat162_rn(v.x, v.y);
        __nv_bfloat162 q1 = __floats2bfloat162_rn(v.z, v.w);
        uint2 u;
        u.x = *reinterpret_cast<unsigned*>(&q0);
        u.y = *reinterpret_cast<unsigned*>(&q1);
        g_xh[idx] = u;
    } else {
        for (int i = tid; i < 512; i += 256) sWp[i] = Wp[i];
        __syncthreads();
        int t = tid;
        if (t < 128) {
            float a[8] = {0, 0, 0, 0, 0, 0, 0, 0};
#pragma unroll 4
            for (int j = 0; j < D; j++) {
                float ws = Ws2[t * D + j];
                float wn = Wn2[t * D + j];
                float p0 = sWp[j * 2], p1 = sWp[j * 2 + 1];
                float q0 = sWp[(128 + j) * 2], q1 = sWp[(128 + j) * 2 + 1];
                a[0] += ws * p0; a[1] += ws * p1;
                a[2] += wn * p0; a[3] += wn * p1;
                a[4] += ws * q0; a[5] += ws * q1;
                a[6] += wn * q0; a[7] += wn * q1;
            }
#pragma unroll
            for (int j = 0; j < 8; j++) g_wc[t * 8 + j] = a[j];
        }
        if (t < 4) {
            int half = t >> 1, c = t & 1;
            float s = 0.f;
            for (int j = 0; j < D; j++)
                s += b2[j] * sWp[(half * 128 + j) * 2 + c];
            g_c[t] = s;
        }
    }
}

// ---------------- pull-based mean aggregation over bf16 x ------------------
__global__ void k_agg(const float* __restrict__ unused) {
    int gid = blockIdx.x * blockDim.x + threadIdx.x;
    int n = gid >> 5;
    int lane = gid & 31;
    if (n >= N_NODES) return;
    int beg = n * CAP;
    int d = g_cnt[n];
    float ax = 0.f, ay = 0.f, az = 0.f, aw = 0.f;
    for (int base = 0; base < d; base += 32) {
        int my = -1;
        if (base + lane < d) my = g_csr[beg + base + lane];
        int cnt = min(32, d - base);
        int j = 0;
        for (; j + 4 <= cnt; j += 4) {
            int s0 = __shfl_sync(0xffffffffu, my, j);
            int s1 = __shfl_sync(0xffffffffu, my, j + 1);
            int s2 = __shfl_sync(0xffffffffu, my, j + 2);
            int s3 = __shfl_sync(0xffffffffu, my, j + 3);
            uint2 u0 = g_xh[s0 * 32 + lane];
            uint2 u1 = g_xh[s1 * 32 + lane];
            uint2 u2 = g_xh[s2 * 32 + lane];
            uint2 u3 = g_xh[s3 * 32 + lane];
            float2 f;
            f = __bfloat1622float2(*reinterpret_cast<__nv_bfloat162*>(&u0.x));
            ax += f.x; ay += f.y;
            f = __bfloat1622float2(*reinterpret_cast<__nv_bfloat162*>(&u0.y));
            az += f.x; aw += f.y;
            f = __bfloat1622float2(*reinterpret_cast<__nv_bfloat162*>(&u1.x));
            ax += f.x; ay += f.y;
            f = __bfloat1622float2(*reinterpret_cast<__nv_bfloat162*>(&u1.y));
            az += f.x; aw += f.y;
            f = __bfloat1622float2(*reinterpret_cast<__nv_bfloat162*>(&u2.x));
            ax += f.x; ay += f.y;
            f = __bfloat1622float2(*reinterpret_cast<__nv_bfloat162*>(&u2.y));
            az += f.x; aw += f.y;
            f = __bfloat1622float2(*reinterpret_cast<__nv_bfloat162*>(&u3.x));
            ax += f.x; ay += f.y;
            f = __bfloat1622float2(*reinterpret_cast<__nv_bfloat162*>(&u3.y));
            az += f.x; aw += f.y;
        }
        for (; j < cnt; j++) {
            int s0 = __shfl_sync(0xffffffffu, my, j);
            uint2 u0 = g_xh[s0 * 32 + lane];
            float2 f;
            f = __bfloat1622float2(*reinterpret_cast<__nv_bfloat162*>(&u0.x));
            ax += f.x; ay += f.y;
            f = __bfloat1622float2(*reinterpret_cast<__nv_bfloat162*>(&u0.y));
            az += f.x; aw += f.y;
        }
    }
    float inv = 1.0f / (float)(d < 1 ? 1 : d);
    float4 r;
    r.x = ax * inv; r.y = ay * inv; r.z = az * inv; r.w = aw * inv;
    *(float4*)(g_agg + (size_t)n * D + lane * 4) = r;
}

// -------- mma.sync tf32 layer 1 + fused projection -------------------------
// CTA = 128 nodes x 128 cols. Two K=128 passes (X@Ws then +M@Wn) sharing
// smem A/B tiles. 8 warps: wm = wid&3 (32 rows), wn = wid>>2 (64 cols).
// Epilogue: relu(C+b1) staged to smem, 2 threads/node project through Wc.
#define ASTR 132   // 128 + 4 pad (u32 units)

__global__ void __launch_bounds__(256, 1)
k_layer_mma(const float* __restrict__ x, const float* __restrict__ agg,
            const float* __restrict__ Wself, const float* __restrict__ Wneigh,
            const float* __restrict__ bias) {
    extern __shared__ uint32_t smu[];
    uint32_t* sA = smu;                    // 128*ASTR (A tf32, later h floats)
    uint32_t* sB = smu + 128 * ASTR;       // 128*ASTR (B tf32)
    float* sWc = (float*)(smu + 2 * 128 * ASTR);   // 1024
    float* sBias = sWc + 1024;                     // 128

    int tid = threadIdx.x;
    int wid = tid >> 5;
    int lane = tid & 31;
    int nb = blockIdx.x * 128;
    int valid = min(128, N_NODES - nb);

    // ---- load pass 1 tiles: A = X rows (tf32), B = Ws (row-major [k][n]) --
    for (int it = tid; it < 128 * 32; it += 256) {
        int r = it >> 5, q = it & 31;
        float4 vx = make_float4(0.f, 0.f, 0.f, 0.f);
        if (r < valid) vx = ((const float4*)x)[(size_t)(nb + r) * 32 + q];
        uint32_t* a = sA + r * ASTR + q * 4;
        a[0] = f2tf32(vx.x); a[1] = f2tf32(vx.y);
        a[2] = f2tf32(vx.z); a[3] = f2tf32(vx.w);
        float4 w = ((const float4*)Wself)[it];
        uint32_t* bp = sB + r * ASTR + q * 4;
        bp[0] = f2tf32(w.x); bp[1] = f2tf32(w.y);
        bp[2] = f2tf32(w.z); bp[3] = f2tf32(w.w);
    }
    for (int i = tid; i < D * 2; i += 256)
        ((float4*)sWc)[i] = ((const float4*)g_wc)[i];
    if (tid < 32) ((float4*)sBias)[tid] = ((const float4*)bias)[tid];
    __syncthreads();

    int wm = wid & 3;        // row block: 32*wm
    int wn = wid >> 2;       // col block: 64*wn
    int tg = lane >> 2;      // thread group 0..7
    int tq = lane & 3;       // 0..3

    float c[2][8][4];
#pragma unroll
    for (int mi = 0; mi < 2; mi++)
#pragma unroll
        for (int ni = 0; ni < 8; ni++)
#pragma unroll
            for (int k = 0; k < 4; k++) c[mi][ni][k] = 0.f;

#pragma unroll 1
    for (int pass = 0; pass < 2; pass++) {
#pragma unroll 2
        for (int kc = 0; kc < 16; kc++) {
            int k0 = kc * 8;
            uint32_t a[2][4];
#pragma unroll
            for (int mi = 0; mi < 2; mi++) {
                int row = 32 * wm + 16 * mi + tg;
                a[mi][0] = sA[row * ASTR + k0 + tq];
                a[mi][1] = sA[(row + 8) * ASTR + k0 + tq];
                a[mi][2] = sA[row * ASTR + k0 + tq + 4];
                a[mi][3] = sA[(row + 8) * ASTR + k0 + tq + 4];
            }
#pragma unroll
            for (int ni = 0; ni < 8; ni++) {
                int col = 64 * wn + 8 * ni + tg;
                uint32_t b0 = sB[(k0 + tq) * ASTR + col];
                uint32_t b1 = sB[(k0 + tq + 4) * ASTR + col];
                mma_tf32(c[0][ni], a[0], b0, b1);
                mma_tf32(c[1][ni], a[1], b0, b1);
            }
        }
        if (pass == 0) {
            __syncthreads();
            // ---- load pass 2 tiles: A = agg rows, B = Wneigh ----
            for (int it = tid; it < 128 * 32; it += 256) {
                int r = it >> 5, q = it & 31;
                float4 vm = make_float4(0.f, 0.f, 0.f, 0.f);
                if (r < valid)
                    vm = ((const float4*)agg)[(size_t)(nb + r) * 32 + q];
                uint32_t* a = sA + r * ASTR + q * 4;
                a[0] = f2tf32(vm.x); a[1] = f2tf32(vm.y);
                a[2] = f2tf32(vm.z); a[3] = f2tf32(vm.w);
                float4 w = ((const float4*)Wneigh)[it];
                uint32_t* bp = sB + r * ASTR + q * 4;
                bp[0] = f2tf32(w.x); bp[1] = f2tf32(w.y);
                bp[2] = f2tf32(w.z); bp[3] = f2tf32(w.w);
            }
            __syncthreads();
        }
    }

    // ---- epilogue: h = relu(C + bias) -> smem (reuse sA as float tile) ----
    __syncthreads();
    float* sH = (float*)sA;
#pragma unroll
    for (int mi = 0; mi < 2; mi++) {
        int r0 = 32 * wm + 16 * mi + tg;
#pragma unroll
        for (int ni = 0; ni < 8; ni++) {
            int cb = 64 * wn + 8 * ni + 2 * tq;
            sH[r0 * ASTR + cb] = fmaxf(c[mi][ni][0] + sBias[cb], 0.f);
            sH[r0 * ASTR + cb + 1] = fmaxf(c[mi][ni][1] + sBias[cb + 1], 0.f);
            sH[(r0 + 8) * ASTR + cb] = fmaxf(c[mi][ni][2] + sBias[cb], 0.f);
            sH[(r0 + 8) * ASTR + cb + 1] =
                fmaxf(c[mi][ni][3] + sBias[cb + 1], 0.f);
        }
    }
    __syncthreads();

    // ---- projection: 2 threads per node, 64 cols each, combine via shfl ---
    int node = tid >> 1;
    int half = tid & 1;
    float pv[8] = {0, 0, 0, 0, 0, 0, 0, 0};
    const float* hrow = sH + node * ASTR + half * 64;
#pragma unroll 8
    for (int j = 0; j < 64; j++) {
        float h = hrow[j];
        int col = half * 64 + j;
        float4 w0 = *(const float4*)(sWc + col * 8);
        float4 w1 = *(const float4*)(sWc + col * 8 + 4);
        pv[0] += h * w0.x; pv[1] += h * w0.y;
        pv[2] += h * w0.z; pv[3] += h * w0.w;
        pv[4] += h * w1.x; pv[5] += h * w1.y;
        pv[6] += h * w1.z; pv[7] += h * w1.w;
    }
#pragma unroll
    for (int m = 0; m < 8; m++)
        pv[m] += __shfl_xor_sync(0xffffffffu, pv[m], 1);
    int gn = nb + node;
    if (half == 0 && gn < N_NODES) {
        g_vself[gn] = make_float4(pv[0], pv[1], pv[4], pv[5]);
        g_vnb[gn] = make_float4(pv[2], pv[3], pv[6], pv[7]);
    }
}

// ---------------- tiny aggregation over 4-float projections ----------------
// one warp per node; both gather chains issued up-front (deg<=64 fast path).
// Also zeroes g_cnt for the next graph replay.
__global__ void k_agg2() {
    int gid = blockIdx.x * blockDim.x + threadIdx.x;
    int n = gid >> 5;
    int lane = gid & 31;
    if (n >= N_NODES) return;
    int beg = n * CAP;
    int d = g_cnt[n];
    int s0 = (lane < d) ? g_csr[beg + lane] : -1;
    int s1 = (lane + 32 < d) ? g_csr[beg + lane + 32] : -1;
    float ax = 0.f, ay = 0.f, az = 0.f, aw = 0.f;
    if (s0 >= 0) {
        float4 v = g_vnb[s0];
        ax += v.x; ay += v.y; az += v.z; aw += v.w;
    }
    if (s1 >= 0) {
        float4 v = g_vnb[s1];
        ax += v.x; ay += v.y; az += v.z; aw += v.w;
    }
    for (int base = 64; base < d; base += 32) {   // rare tail (deg > 64)
        int i = base + lane;
        if (i < d) {
            int s = g_csr[beg + i];
            float4 v = g_vnb[s];
            ax += v.x; ay += v.y; az += v.z; aw += v.w;
        }
    }
#pragma unroll
    for (int off = 16; off > 0; off >>= 1) {
        ax += __shfl_down_sync(0xffffffffu, ax, off);
        ay += __shfl_down_sync(0xffffffffu, ay, off);
        az += __shfl_down_sync(0xffffffffu, az, off);
        aw += __shfl_down_sync(0xffffffffu, aw, off);
    }
    if (lane == 0) {
        float inv = 1.0f / (float)(d < 1 ? 1 : d);
        float4 vs = g_vself[n];
        g_ps[n] = make_float2(vs.x + ax * inv, vs.y + ay * inv);
        g_pd[n] = make_float2(vs.z + az * inv, vs.w + aw * inv);
        g_cnt[n] = 0;   // restore invariant for next replay
    }
}

// ---------------- edge scores: 8 edges per thread --------------------------
__global__ void k_edge(const int* __restrict__ src, const int* __restrict__ dst,
                       const float* __restrict__ bpred,
                       float* __restrict__ out) {
    int t = blockIdx.x * blockDim.x + threadIdx.x;
    if (t * 8 >= N_EDGES) return;
    float b0 = __ldg(bpred) + g_c[0] + g_c[2];
    float b1 = __ldg(bpred + 1) + g_c[1] + g_c[3];
    int4 s0 = ((const int4*)src)[2 * t], s1 = ((const int4*)src)[2 * t + 1];
    int4 d0 = ((const int4*)dst)[2 * t], d1 = ((const int4*)dst)[2 * t + 1];
    float2 a0 = g_ps[s0.x], a1 = g_ps[s0.y], a2 = g_ps[s0.z], a3 = g_ps[s0.w];
    float2 a4 = g_ps[s1.x], a5 = g_ps[s1.y], a6 = g_ps[s1.z], a7 = g_ps[s1.w];
    float2 c0 = g_pd[d0.x], c1 = g_pd[d0.y], c2 = g_pd[d0.z], c3 = g_pd[d0.w];
    float2 c4 = g_pd[d1.x], c5 = g_pd[d1.y], c6 = g_pd[d1.z], c7 = g_pd[d1.w];
    float4 o;
    o = make_float4(a0.x + c0.x + b0, a0.y + c0.y + b1,
                    a1.x + c1.x + b0, a1.y + c1.y + b1);
    ((float4*)out)[t * 4] = o;
    o = make_float4(a2.x + c2.x + b0, a2.y + c2.y + b1,
                    a3.x + c3.x + b0, a3.y + c3.y + b1);
    ((float4*)out)[t * 4 + 1] = o;
    o = make_float4(a4.x + c4.x + b0, a4.y + c4.y + b1,
                    a5.x + c5.x + b0, a5.y + c5.y + b1);
    ((float4*)out)[t * 4 + 2] = o;
    o = make_float4(a6.x + c6.x + b0, a6.y + c6.y + b1,
                    a7.x + c7.x + b0, a7.y + c7.y + b1);
    ((float4*)out)[t * 4 + 3] = o;
}

// ---------------- launcher -------------------------------------------------
extern "C" void kernel_launch(void* const* d_in, const int* in_sizes, int n_in,
                              void* d_out, int out_size) {
    const float* x = (const float*)d_in[0];
    const int* src = (const int*)d_in[1];
    const int* dst = (const int*)d_in[2];
    const float* Wself1 = (const float*)d_in[3];
    const float* Wneigh1 = (const float*)d_in[4];
    const float* b1 = (const float*)d_in[5];
    const float* Wself2 = (const float*)d_in[6];
    const float* Wneigh2 = (const float*)d_in[7];
    const float* b2 = (const float*)d_in[8];
    const float* Wpred = (const float*)d_in[9];
    const float* bpred = (const float*)d_in[10];
    float* out = (float*)d_out;

    size_t layer_smem = (size_t)(2 * 128 * ASTR + 1024 + 128) * 4;
    cudaFuncSetAttribute(k_layer_mma,
                         cudaFuncAttributeMaxDynamicSharedMemorySize,
                         (int)layer_smem);

    float* p_agg;
    cudaGetSymbolAddress((void**)&p_agg, g_agg);

    const int TPB = 256;
    int warp_blocks = (N_NODES * 32 + TPB - 1) / TPB;

    k_prep<<<FILL_BLOCKS + CVT_BLOCKS + 1, TPB>>>(src, dst, x, Wself2, Wneigh2,
                                                  b2, Wpred);
    k_agg<<<warp_blocks, TPB>>>(x);
    k_layer_mma<<<GEMM_BLOCKS, TPB, layer_smem>>>(x, p_agg, Wself1, Wneigh1,
                                                  b1);
    k_agg2<<<warp_blocks, TPB>>>();
    k_edge<<<FILL_BLOCKS, TPB>>>(src, dst, bpred, out);
}